// round 6
// baseline (speedup 1.0000x reference)
#include <cuda_runtime.h>
#include <math.h>

#define B_ 4
#define T_ 8
#define C_ 128
#define HW_ 9216          // 96*96
#define NBT 32            // B*T
#define NCHUNK 72
#define CHUNK 16384
#define TILEP 32
#define NTILE 288         // HW_/TILEP

typedef unsigned long long ull;

__device__ __forceinline__ ull pack2(float a, float b) {
    ull r; asm("mov.b64 %0,{%1,%2};" : "=l"(r) : "f"(a), "f"(b)); return r;
}
__device__ __forceinline__ void unpack2(ull v, float& a, float& b) {
    asm("mov.b64 {%0,%1},%2;" : "=f"(a), "=f"(b) : "l"(v));
}
__device__ __forceinline__ ull fma2(ull a, ull b, ull c) {
    ull d; asm("fma.rn.f32x2 %0,%1,%2,%3;" : "=l"(d) : "l"(a), "l"(b), "l"(c)); return d;
}
__device__ __forceinline__ ull mul2(ull a, ull b) {
    ull d; asm("mul.rn.f32x2 %0,%1,%2;" : "=l"(d) : "l"(a), "l"(b)); return d;
}

// deterministic scratch
__device__ float g_psum[NBT * NCHUNK];
__device__ float g_psq [NBT * NCHUNK];
__device__ float g_A[NBT * C_];
__device__ float g_Bc[NBT * C_];
__device__ float g_WkT[C_ * C_];   // [c][h*32+d] = qkv_w[128 + h*32+d][c] * scale

// ---------------- Kernel 1: partial sums per (b,t) chunk ----------------
__global__ __launch_bounds__(256) void reduce_kernel(const float* __restrict__ x,
                                                     const float* __restrict__ pos) {
    int bt    = blockIdx.x / NCHUNK;
    int chunk = blockIdx.x % NCHUNK;
    int t     = bt & (T_ - 1);
    const float4* x4 = (const float4*)(x + (size_t)bt * C_ * HW_);
    int base4 = chunk * (CHUNK / 4);
    float s = 0.f, sq = 0.f;
#pragma unroll
    for (int i = 0; i < 16; i++) {
        int e4 = base4 + i * 256 + threadIdx.x;
        int c  = e4 / 2304;
        float pv = pos[t * C_ + c];
        float4 v = x4[e4];
        float a0 = v.x + pv, a1 = v.y + pv, a2 = v.z + pv, a3 = v.w + pv;
        s  += (a0 + a1) + (a2 + a3);
        sq += (a0 * a0 + a1 * a1) + (a2 * a2 + a3 * a3);
    }
    __shared__ float ss[8], ssq[8];
#pragma unroll
    for (int o = 16; o; o >>= 1) {
        s  += __shfl_down_sync(0xFFFFFFFFu, s, o);
        sq += __shfl_down_sync(0xFFFFFFFFu, sq, o);
    }
    int w = threadIdx.x >> 5;
    if ((threadIdx.x & 31) == 0) { ss[w] = s; ssq[w] = sq; }
    __syncthreads();
    if (threadIdx.x == 0) {
        float S = 0.f, SQ = 0.f;
#pragma unroll
        for (int i = 0; i < 8; i++) { S += ss[i]; SQ += ssq[i]; }
        g_psum[bt * NCHUNK + chunk] = S;
        g_psq [bt * NCHUNK + chunk] = SQ;
    }
}

// ---------------- Kernel 2: finalize mean/rstd -> affine A,B ----------------
__global__ __launch_bounds__(256) void finalize_kernel(const float* __restrict__ pos,
                                                       const float* __restrict__ nw,
                                                       const float* __restrict__ nb) {
    __shared__ float sm[NBT], sr[NBT];
    int tid = threadIdx.x;
    if (tid < NBT) {
        float S = 0.f, SQ = 0.f;
        for (int i = 0; i < NCHUNK; i++) { S += g_psum[tid * NCHUNK + i]; SQ += g_psq[tid * NCHUNK + i]; }
        const float invN = 1.0f / (float)(C_ * HW_);
        float mean = S * invN;
        float var  = SQ * invN - mean * mean;
        sm[tid] = mean;
        sr[tid] = rsqrtf(var + 1e-5f);
    }
    __syncthreads();
    for (int idx = tid; idx < NBT * C_; idx += 256) {
        int bt = idx >> 7, c = idx & 127, t = bt & (T_ - 1);
        float a = sr[bt] * nw[c];
        g_A[idx]  = a;
        g_Bc[idx] = (pos[t * C_ + c] - sm[bt]) * a + nb[c];
    }
}

// ---------------- Kernel 2b: transpose Wk (attention scale folded in) ----------------
__global__ __launch_bounds__(256) void wkT_kernel(const float* __restrict__ qkv_w) {
    int i = blockIdx.x * 256 + threadIdx.x;   // 0..16383
    int c = i >> 7, hd = i & 127;
    g_WkT[c * 128 + hd] = qkv_w[(128 + hd) * 128 + c] * 0.17677669529663687f;
}

// ---------------- Kernel 3: fused main (512 threads) ----------------
// smem float offsets
#define SM_XN   0                     // 128*32 = 4096 (t=7 tile only)
#define SM_BIG  4096                  // 4*128*32 = 16384 (U, then XBAR)
#define SM_Q    20480                 // 128*32 = 4096 (Q, then Out)
#define SM_P    24576                 // 1024 (logit partials: half*8+cld groups, float2)
#define SM_AB   25600                 // 2048 (A then B, [t*128+c])
#define SMEM_FLOATS 27648
#define SMEM_BYTES (SMEM_FLOATS * 4)  // 110592

// 2-output-row x 32-pixel packed GEMM core (weights packed in regs)
__device__ __forceinline__ void gemm2(const float* __restrict__ wrow,
                                      const float* __restrict__ xsrc,
                                      int pg, int kdim, ull acc[2][2]) {
#pragma unroll
    for (int i = 0; i < 2; i++) { acc[i][0] = 0ull; acc[i][1] = 0ull; }
#pragma unroll 4
    for (int k = 0; k < kdim; k += 4) {
        ull xv[4][2];
#pragma unroll
        for (int kk = 0; kk < 4; kk++) {
            ulonglong2 v = *(const ulonglong2*)(xsrc + (k + kk) * 32 + pg * 4);
            xv[kk][0] = v.x; xv[kk][1] = v.y;
        }
#pragma unroll
        for (int i = 0; i < 2; i++) {
            float4 wv = *(const float4*)(wrow + i * C_ + k);
            ull w0 = pack2(wv.x, wv.x), w1 = pack2(wv.y, wv.y);
            ull w2 = pack2(wv.z, wv.z), w3 = pack2(wv.w, wv.w);
            acc[i][0] = fma2(w0, xv[0][0], acc[i][0]); acc[i][1] = fma2(w0, xv[0][1], acc[i][1]);
            acc[i][0] = fma2(w1, xv[1][0], acc[i][0]); acc[i][1] = fma2(w1, xv[1][1], acc[i][1]);
            acc[i][0] = fma2(w2, xv[2][0], acc[i][0]); acc[i][1] = fma2(w2, xv[2][1], acc[i][1]);
            acc[i][0] = fma2(w3, xv[3][0], acc[i][0]); acc[i][1] = fma2(w3, xv[3][1], acc[i][1]);
        }
    }
}

__global__ __launch_bounds__(512, 1) void main_kernel(const float* __restrict__ x,
                                                      const float* __restrict__ qkv_w,
                                                      const float* __restrict__ proj_w,
                                                      float* __restrict__ out) {
    extern __shared__ float sm[];
    float* sXN  = sm + SM_XN;
    float* sBig = sm + SM_BIG;
    float* sQ   = sm + SM_Q;
    float* sP   = sm + SM_P;
    float* sAB  = sm + SM_AB;

    int b    = blockIdx.x / NTILE;
    int tile = blockIdx.x % NTILE;
    int hw0  = tile * TILEP;
    int tid  = threadIdx.x;
    int rgrp = tid >> 3;          // GEMM layout: 0..63 -> rows rgrp*2, rgrp*2+1
    int pg   = tid & 7;           // GEMM layout: pixel group
    int half = tid >> 8;          // attention: 0/1 -> heads {2*half, 2*half+1}
    int cld  = (tid >> 5) & 7;    // attention: c-set {cld+8j}
    int pld  = tid & 31;          // attention: pixel

    // ---- stage A/B affine tables for this b ----
    for (int idx = tid; idx < 1024; idx += 512) {
        sAB[idx]        = g_A [b * T_ * C_ + idx];
        sAB[1024 + idx] = g_Bc[b * T_ * C_ + idx];
    }

    // ---- Phase A: normalized tile at t=T-1 ----
    {
        int bt = b * T_ + (T_ - 1);
        const float* xb = x + (size_t)bt * C_ * HW_;
        const float* Ab = g_A  + bt * C_;
        const float* Bb = g_Bc + bt * C_;
#pragma unroll
        for (int i = tid; i < 4096; i += 512) {
            int c = i >> 5, p = i & 31;
            sXN[i] = xb[c * HW_ + hw0 + p] * Ab[c] + Bb[c];
        }
    }
    __syncthreads();

    // prefetch t=0 raw x (attention layout; both halves duplicate)
    float xr[16];
    {
        const float* xb = x + (size_t)(b * T_) * C_ * HW_;
#pragma unroll
        for (int jj = 0; jj < 8; jj++) {
            xr[2 * jj]     = xb[(cld + 16 * jj    ) * HW_ + hw0 + pld];
            xr[2 * jj + 1] = xb[(cld + 16 * jj + 8) * HW_ + hw0 + pld];
        }
    }

    // ---- Q GEMM (scale folded into WkT) -> sQ ----
    {
        ull acc[2][2];
        gemm2(qkv_w + (size_t)(rgrp * 2) * C_, sXN, pg, 128, acc);
#pragma unroll
        for (int i = 0; i < 2; i++) {
            ulonglong2 o; o.x = acc[i][0]; o.y = acc[i][1];
            *(ulonglong2*)(sQ + (rgrp * 2 + i) * 32 + pg * 4) = o;
        }
    }
    __syncthreads();

    // ---- U_h[c][p] = sum_d WkT[c][h*32+d]*Q[h*32+d][p] -> sBig ----
#pragma unroll
    for (int h = 0; h < 4; h++) {
        ull acc[2][2];
        gemm2(g_WkT + (size_t)(rgrp * 2) * C_ + h * 32, sQ + h * 1024, pg, 32, acc);
#pragma unroll
        for (int i = 0; i < 2; i++) {
            ulonglong2 o; o.x = acc[i][0]; o.y = acc[i][1];
            *(ulonglong2*)(sBig + h * 4096 + (rgrp * 2 + i) * 32 + pg * 4) = o;
        }
    }
    __syncthreads();

    // ---- load this half's 2 heads of U into regs, packed over c-pairs (c, c+8) ----
    int h0 = half * 2;
    ull uP[2][8];
#pragma unroll
    for (int h2 = 0; h2 < 2; h2++)
#pragma unroll
        for (int jj = 0; jj < 8; jj++) {
            float a0 = sBig[(h0 + h2) * 4096 + (cld + 16 * jj    ) * 32 + pld];
            float a1 = sBig[(h0 + h2) * 4096 + (cld + 16 * jj + 8) * 32 + pld];
            uP[h2][jj] = pack2(a0, a1);
        }

    // xn for t=7 from sXN
    ull xnP[8];
#pragma unroll
    for (int jj = 0; jj < 8; jj++) {
        float a0 = sXN[(cld + 16 * jj    ) * 32 + pld];
        float a1 = sXN[(cld + 16 * jj + 8) * 32 + pld];
        xnP[jj] = pack2(a0, a1);
    }

    // register-resident online softmax + xbar (2 heads per thread)
    ull   xbarP[2][8];
#pragma unroll
    for (int h2 = 0; h2 < 2; h2++)
#pragma unroll
        for (int jj = 0; jj < 8; jj++) xbarP[h2][jj] = 0ull;
    float m_run[2] = {-1e30f, -1e30f};
    float s_run[2] = {0.f, 0.f};

    for (int it = 0; it < T_; it++) {
        int s = (it == 0) ? (T_ - 1) : (it - 1);
        if (it > 0) {
            const float* As = sAB + s * 128;
            const float* Bs = sAB + 1024 + s * 128;
#pragma unroll
            for (int jj = 0; jj < 8; jj++) {
                int c0 = cld + 16 * jj;
                float a0 = xr[2 * jj]     * As[c0]     + Bs[c0];
                float a1 = xr[2 * jj + 1] * As[c0 + 8] + Bs[c0 + 8];
                xnP[jj] = pack2(a0, a1);
            }
        }
        if (it >= 1 && it < T_ - 1) {   // prefetch raw x for t=it (used next iter)
            const float* xb = x + (size_t)(b * T_ + it) * C_ * HW_;
#pragma unroll
            for (int jj = 0; jj < 8; jj++) {
                xr[2 * jj]     = xb[(cld + 16 * jj    ) * HW_ + hw0 + pld];
                xr[2 * jj + 1] = xb[(cld + 16 * jj + 8) * HW_ + hw0 + pld];
            }
        }

        // logit partials for this half's 2 heads over 16 c
        ull lg[2] = {0ull, 0ull};
#pragma unroll
        for (int jj = 0; jj < 8; jj++) {
            lg[0] = fma2(xnP[jj], uP[0][jj], lg[0]);
            lg[1] = fma2(xnP[jj], uP[1][jj], lg[1]);
        }
        float2 part;
        { float lo, hi;
          unpack2(lg[0], lo, hi); part.x = lo + hi;
          unpack2(lg[1], lo, hi); part.y = lo + hi; }
        *(float2*)(sP + ((half * 8 + cld) * 32 + pld) * 2) = part;
        __syncthreads();

        // reduce this half's 8 partials (redundant per pixel, deterministic)
        float L[2] = {0.f, 0.f};
#pragma unroll
        for (int k = 0; k < 8; k++) {
            float2 v = *(const float2*)(sP + ((half * 8 + k) * 32 + pld) * 2);
            L[0] += v.x; L[1] += v.y;
        }
        __syncthreads();   // sP free for next iteration

        // softmax state + xbar update
#pragma unroll
        for (int h2 = 0; h2 < 2; h2++) {
            float mn   = fmaxf(m_run[h2], L[h2]);
            float corr = __expf(m_run[h2] - mn);
            float e    = __expf(L[h2] - mn);
            s_run[h2] = s_run[h2] * corr + e;
            m_run[h2] = mn;
            ull cP = pack2(corr, corr);
            ull eP = pack2(e, e);
#pragma unroll
            for (int jj = 0; jj < 8; jj++)
                xbarP[h2][jj] = fma2(eP, xnP[jj], mul2(cP, xbarP[h2][jj]));
        }
    }

    // normalize xbar and write this half's heads into sBig (U dead)
#pragma unroll
    for (int h2 = 0; h2 < 2; h2++) {
        float inv = 1.0f / s_run[h2];
        ull iP = pack2(inv, inv);
#pragma unroll
        for (int jj = 0; jj < 8; jj++) {
            float lo, hi;
            unpack2(mul2(iP, xbarP[h2][jj]), lo, hi);
            sBig[(h0 + h2) * 4096 + (cld + 16 * jj    ) * 32 + pld] = lo;
            sBig[(h0 + h2) * 4096 + (cld + 16 * jj + 8) * 32 + pld] = hi;
        }
    }
    __syncthreads();

    // ---- Phase E: Out[hd][p] = Wv . xbar_h -> sQ ----
    {
        ull acc[2][2];
        gemm2(qkv_w + (size_t)(256 + rgrp * 2) * C_, sBig + (rgrp >> 4) * 4096, pg, 128, acc);
#pragma unroll
        for (int i = 0; i < 2; i++) {
            ulonglong2 o; o.x = acc[i][0]; o.y = acc[i][1];
            *(ulonglong2*)(sQ + (rgrp * 2 + i) * 32 + pg * 4) = o;
        }
    }
    __syncthreads();

    // ---- Phase F: projection -> gmem ----
    {
        ull acc[2][2];
        gemm2(proj_w + (size_t)(rgrp * 2) * C_, sQ, pg, 128, acc);
#pragma unroll
        for (int i = 0; i < 2; i++) {
            ulonglong2 o; o.x = acc[i][0]; o.y = acc[i][1];
            *(ulonglong2*)(out + ((size_t)b * C_ + rgrp * 2 + i) * HW_ + hw0 + pg * 4) = o;
        }
    }
}

extern "C" void kernel_launch(void* const* d_in, const int* in_sizes, int n_in,
                              void* d_out, int out_size) {
    const float* x    = (const float*)d_in[0];
    const float* pos  = (const float*)d_in[1];
    const float* nw   = (const float*)d_in[2];
    const float* nb   = (const float*)d_in[3];
    const float* qkvw = (const float*)d_in[4];
    const float* pw   = (const float*)d_in[5];
    float* out = (float*)d_out;

    reduce_kernel<<<NBT * NCHUNK, 256>>>(x, pos);
    finalize_kernel<<<1, 256>>>(pos, nw, nb);
    wkT_kernel<<<64, 256>>>(qkvw);
    cudaFuncSetAttribute(main_kernel, cudaFuncAttributeMaxDynamicSharedMemorySize, SMEM_BYTES);
    main_kernel<<<B_ * NTILE, 512, SMEM_BYTES>>>(x, qkvw, pw, out);
}